// round 1
// baseline (speedup 1.0000x reference)
#include <cuda_runtime.h>

// RLFrameSelector: scores = relu(x@W1 + b1)@W2 + b2 (masked), per-batch top-k
// frame selection, out = x * sel.
//
// Kernel 1: fp32 scores via packed fma.rn.f32x2 (exactness needed: top-k set
//           must match the fp32 reference; score gaps ~3e-3).
// Kernel 2: per-batch radix-select top-k threshold + stable tie-break by index
//           (matches jax.lax.top_k stability).
// Kernel 3: gather/zero output (reads x only for selected frames).

#define BB 32
#define TT 2048
#define FF 512
#define UU 128
#define TM 64        // frames per block in score kernel
#define FC 16        // f-chunk
#define XST 66       // float2 stride per f-row in xs2 (padded)

__device__ float         g_scores[BB * TT];
__device__ unsigned char g_sel[BB * TT];

__device__ __forceinline__ unsigned long long fma2(unsigned long long a,
                                                   unsigned long long b,
                                                   unsigned long long c) {
    unsigned long long d;
    asm("fma.rn.f32x2 %0, %1, %2, %3;" : "=l"(d) : "l"(a), "l"(b), "l"(c));
    return d;
}

__device__ __forceinline__ float2 unpack2(unsigned long long v) {
    float2 r;
    asm("mov.b64 {%0, %1}, %2;" : "=f"(r.x), "=f"(r.y) : "l"(v));
    return r;
}

// ---------------------------------------------------------------------------
// Kernel 1: scores. Block = 256 threads = 16 (tx, frames) x 16 (ty, units).
// Thread tile: 4 frames x 8 units (4 u-pairs as f32x2 accumulators).
// ---------------------------------------------------------------------------
__global__ __launch_bounds__(256) void score_kernel(
    const float* __restrict__ x,  const float* __restrict__ W1,
    const float* __restrict__ b1, const float* __restrict__ W2,
    const float* __restrict__ b2)
{
    __shared__ float2 xs2[FC * XST];       // [f][t], each entry = (x, x) dup
    __shared__ float  ws[FC * UU];         // [f][u]
    __shared__ int    nzflag[TM];
    __shared__ float  red[16][TM + 1];     // partial scores per ty-group

    const int tid = threadIdx.x;
    const int tx  = tid & 15;              // frame group (4 frames each)
    const int ty  = tid >> 4;              // unit group  (8 units each)
    const int blk = blockIdx.x;
    const int frame0 = blk * TM;

    // loader mapping
    const int lrow = tid >> 2;             // 0..63
    const int lg   = tid & 3;              // 0..3 (16 floats per row per chunk)

    if (tid < TM) nzflag[tid] = 0;

    unsigned long long acc[4][4];
#pragma unroll
    for (int t = 0; t < 4; ++t)
#pragma unroll
        for (int up = 0; up < 4; ++up) acc[t][up] = 0ull;

    int nz = 0;
    const float* xrow = x + (size_t)(frame0 + lrow) * FF + 4 * lg;

#pragma unroll 1
    for (int chunk = 0; chunk < FF / FC; ++chunk) {
        // global loads for this chunk
        const float4 xv  = *(const float4*)(xrow + chunk * FC);
        const float4* wsrc = (const float4*)(W1 + chunk * FC * UU);
        const float4 wv0 = wsrc[tid];
        const float4 wv1 = wsrc[tid + 256];

        nz |= (xv.x != 0.0f) | (xv.y != 0.0f) | (xv.z != 0.0f) | (xv.w != 0.0f);

        __syncthreads();   // previous compute done before overwrite
        xs2[(4 * lg + 0) * XST + lrow] = make_float2(xv.x, xv.x);
        xs2[(4 * lg + 1) * XST + lrow] = make_float2(xv.y, xv.y);
        xs2[(4 * lg + 2) * XST + lrow] = make_float2(xv.z, xv.z);
        xs2[(4 * lg + 3) * XST + lrow] = make_float2(xv.w, xv.w);
        ((float4*)ws)[tid]       = wv0;
        ((float4*)ws)[tid + 256] = wv1;
        __syncthreads();

#pragma unroll
        for (int f = 0; f < FC; ++f) {
            const ulonglong2* xp = (const ulonglong2*)(xs2 + f * XST + 4 * tx);
            const ulonglong2 xa = xp[0];   // frames t0,t1 (each dup pair)
            const ulonglong2 xb = xp[1];   // frames t2,t3
            const ulonglong2* wp = (const ulonglong2*)(ws + f * UU + 8 * ty);
            const ulonglong2 wa = wp[0];   // u-pairs 0,1
            const ulonglong2 wb = wp[1];   // u-pairs 2,3

            acc[0][0] = fma2(xa.x, wa.x, acc[0][0]);
            acc[0][1] = fma2(xa.x, wa.y, acc[0][1]);
            acc[0][2] = fma2(xa.x, wb.x, acc[0][2]);
            acc[0][3] = fma2(xa.x, wb.y, acc[0][3]);
            acc[1][0] = fma2(xa.y, wa.x, acc[1][0]);
            acc[1][1] = fma2(xa.y, wa.y, acc[1][1]);
            acc[1][2] = fma2(xa.y, wb.x, acc[1][2]);
            acc[1][3] = fma2(xa.y, wb.y, acc[1][3]);
            acc[2][0] = fma2(xb.x, wa.x, acc[2][0]);
            acc[2][1] = fma2(xb.x, wa.y, acc[2][1]);
            acc[2][2] = fma2(xb.x, wb.x, acc[2][2]);
            acc[2][3] = fma2(xb.x, wb.y, acc[2][3]);
            acc[3][0] = fma2(xb.y, wa.x, acc[3][0]);
            acc[3][1] = fma2(xb.y, wa.y, acc[3][1]);
            acc[3][2] = fma2(xb.y, wb.x, acc[3][2]);
            acc[3][3] = fma2(xb.y, wb.y, acc[3][3]);
        }
    }

    // epilogue: relu + second layer partial dot
    float p[4] = {0.f, 0.f, 0.f, 0.f};
#pragma unroll
    for (int up = 0; up < 4; ++up) {
        const int u = 8 * ty + 2 * up;
        const float b1lo = b1[u],     b1hi = b1[u + 1];
        const float w2lo = W2[u],     w2hi = W2[u + 1];
#pragma unroll
        for (int t = 0; t < 4; ++t) {
            const float2 hv = unpack2(acc[t][up]);
            p[t] += fmaxf(hv.x + b1lo, 0.0f) * w2lo
                  + fmaxf(hv.y + b1hi, 0.0f) * w2hi;
        }
    }

    __syncthreads();   // protect xs2/ws reads (red is separate, but keep order)
#pragma unroll
    for (int t = 0; t < 4; ++t) red[ty][4 * tx + t] = p[t];
    if (nz) nzflag[lrow] = 1;
    __syncthreads();

    if (tid < TM) {
        float s = 0.0f;
#pragma unroll
        for (int j = 0; j < 16; ++j) s += red[j][tid];
        s += b2[0];
        g_scores[frame0 + tid] = nzflag[tid] ? s : -1.0e9f;
    }
}

// ---------------------------------------------------------------------------
// Kernel 2: per-batch top-k selection via 4x8-bit radix select on orderable
// uint keys. Ties (==threshold) taken by smallest index (jax top_k stable).
// ---------------------------------------------------------------------------
__global__ __launch_bounds__(256) void topk_kernel(const int* kptr)
{
    __shared__ unsigned keys[TT];
    __shared__ int      hist[256];
    __shared__ unsigned s_prefix;
    __shared__ int      s_remaining;

    const int b   = blockIdx.x;
    const int tid = threadIdx.x;

    int k = 64;
    if (kptr) {
        int kv = *kptr;                 // int32/int64 little-endian low word
        if (kv > 0 && kv <= TT) k = kv;
        else {                          // defensive: maybe stored as float bits
            float kf = __int_as_float(kv);
            if (kf >= 1.0f && kf <= (float)TT) k = (int)kf;
        }
    }

    for (int i = tid; i < TT; i += 256) {
        unsigned u = __float_as_uint(g_scores[b * TT + i]);
        keys[i] = (u & 0x80000000u) ? ~u : (u | 0x80000000u);
    }
    if (tid == 0) { s_prefix = 0u; s_remaining = k; }
    __syncthreads();

    for (int pass = 3; pass >= 0; --pass) {
        hist[tid] = 0;
        __syncthreads();
        const unsigned mhi  = (pass == 3) ? 0u : (0xFFFFFFFFu << ((pass + 1) * 8));
        const unsigned pref = s_prefix;
        const int shift = pass * 8;
        for (int i = tid; i < TT; i += 256) {
            const unsigned ky = keys[i];
            if ((ky & mhi) == pref) atomicAdd(&hist[(ky >> shift) & 255], 1);
        }
        __syncthreads();
        if (tid == 0) {
            int rem = s_remaining, cum = 0, bin;
            for (bin = 255; bin >= 0; --bin) {
                const int c = hist[bin];
                if (cum + c >= rem) break;
                cum += c;
            }
            s_prefix    = pref | ((unsigned)bin << shift);
            s_remaining = rem - cum;
        }
        __syncthreads();
    }

    const unsigned thr = s_prefix;
    const int need = s_remaining;      // how many ==thr to take (smallest index)
    for (int i = tid; i < TT; i += 256) {
        const unsigned ky = keys[i];
        unsigned char sv = 0;
        if (ky > thr) sv = 1;
        else if (ky == thr) {
            int r = 0;
            for (int j = 0; j < i; ++j) r += (keys[j] == thr);
            sv = (r < need) ? 1 : 0;
        }
        g_sel[b * TT + i] = sv;
    }
}

// ---------------------------------------------------------------------------
// Kernel 3: out = sel ? x : 0. Reads x only for selected frames.
// ---------------------------------------------------------------------------
__global__ __launch_bounds__(256) void gather_kernel(
    const float* __restrict__ x, float* __restrict__ out)
{
    const int i = blockIdx.x * 256 + threadIdx.x;   // float4 index
    const int frame = i >> 7;                       // FF/4 = 128 float4/frame
    float4 v = make_float4(0.f, 0.f, 0.f, 0.f);
    if (g_sel[frame]) v = ((const float4*)x)[i];
    ((float4*)out)[i] = v;
}

// ---------------------------------------------------------------------------
extern "C" void kernel_launch(void* const* d_in, const int* in_sizes, int n_in,
                              void* d_out, int out_size)
{
    const float* x  = (const float*)d_in[0];
    const float* W1 = (const float*)d_in[1];
    const float* b1 = (const float*)d_in[2];
    const float* W2 = (const float*)d_in[3];
    const float* b2 = (const float*)d_in[4];
    const int*   kp = (n_in > 5) ? (const int*)d_in[5] : nullptr;

    score_kernel<<<(BB * TT) / TM, 256>>>(x, W1, b1, W2, b2);
    topk_kernel<<<BB, 256>>>(kp);
    gather_kernel<<<(BB * TT * FF / 4) / 256, 256>>>(x, (float*)d_out);
}

// round 2
// speedup vs baseline: 1.5535x; 1.5535x over previous
#include <cuda_runtime.h>

// RLFrameSelector: scores = relu(x@W1 + b1)@W2 + b2 (masked), per-batch top-k
// frame selection, out = x * sel.
//
// R2: score_kernel remapped to kill smem bank conflicts (R1 was L1-bound at
// 75.8% with 4-way conflicts on the x LDS.128). Frame dim now spans all 32
// lanes (conflict-free 16B/lane loads); W loads are warp-broadcast.

#define BB 32
#define TT 2048
#define FF 512
#define UU 128
#define TM 64        // frames per block in score kernel
#define FC 16        // f-chunk
#define XST 66       // float2 stride per f-row in xs2 (528B, 16B-aligned)

__device__ float         g_scores[BB * TT];
__device__ unsigned char g_sel[BB * TT];

__device__ __forceinline__ unsigned long long fma2(unsigned long long a,
                                                   unsigned long long b,
                                                   unsigned long long c) {
    unsigned long long d;
    asm("fma.rn.f32x2 %0, %1, %2, %3;" : "=l"(d) : "l"(a), "l"(b), "l"(c));
    return d;
}

__device__ __forceinline__ float2 unpack2(unsigned long long v) {
    float2 r;
    asm("mov.b64 {%0, %1}, %2;" : "=f"(r.x), "=f"(r.y) : "l"(v));
    return r;
}

// ---------------------------------------------------------------------------
// Kernel 1: scores. Block = 256 threads.
//   tx = tid&31  -> frame pair (frames 2*tx, 2*tx+1)   [spans full warp]
//   ty = tid>>5  -> units 16*ty..16*ty+15 (8 f32x2 u-pairs)  [uniform per warp]
// Thread tile: 2 frames x 16 units = 16 f32x2 accumulators.
// Per f-step: 1 conflict-free LDS.128 (x, dup pairs) + 4 broadcast LDS.128 (W)
//             + 16 fma.rn.f32x2.
// ---------------------------------------------------------------------------
__global__ __launch_bounds__(256) void score_kernel(
    const float* __restrict__ x,  const float* __restrict__ W1,
    const float* __restrict__ b1, const float* __restrict__ W2,
    const float* __restrict__ b2)
{
    __shared__ float2 xs2[FC * XST];       // [f][t], entry = (x, x) dup
    __shared__ float  ws[FC * UU];         // [f][u] (matches W1 row-major)
    __shared__ int    nzflag[TM];
    __shared__ float  red[8][TM + 2];      // partial scores per ty-group

    const int tid = threadIdx.x;
    const int tx  = tid & 31;              // frame pair
    const int ty  = tid >> 5;              // unit group (16 units)
    const int frame0 = blockIdx.x * TM;

    // loader mapping (x): row = tid>>2 (0..63), group = tid&3
    const int lrow = tid >> 2;
    const int lg   = tid & 3;

    if (tid < TM) nzflag[tid] = 0;

    unsigned long long acc[2][8];
#pragma unroll
    for (int t = 0; t < 2; ++t)
#pragma unroll
        for (int p = 0; p < 8; ++p) acc[t][p] = 0ull;

    int nz = 0;
    const float* xrow = x + (size_t)(frame0 + lrow) * FF + 4 * lg;

#pragma unroll 1
    for (int chunk = 0; chunk < FF / FC; ++chunk) {
        // global loads for this chunk
        const float4 xv  = *(const float4*)(xrow + chunk * FC);
        const float4* wsrc = (const float4*)(W1 + chunk * FC * UU);
        const float4 wv0 = wsrc[tid];
        const float4 wv1 = wsrc[tid + 256];

        nz |= (xv.x != 0.0f) | (xv.y != 0.0f) | (xv.z != 0.0f) | (xv.w != 0.0f);

        __syncthreads();   // previous compute done before overwrite
        xs2[(4 * lg + 0) * XST + lrow] = make_float2(xv.x, xv.x);
        xs2[(4 * lg + 1) * XST + lrow] = make_float2(xv.y, xv.y);
        xs2[(4 * lg + 2) * XST + lrow] = make_float2(xv.z, xv.z);
        xs2[(4 * lg + 3) * XST + lrow] = make_float2(xv.w, xv.w);
        ((float4*)ws)[tid]       = wv0;
        ((float4*)ws)[tid + 256] = wv1;
        __syncthreads();

#pragma unroll
        for (int f = 0; f < FC; ++f) {
            // x: frames 2*tx, 2*tx+1 duplicated; 16B per lane, stride 16B
            const ulonglong2 xa =
                *(const ulonglong2*)(xs2 + f * XST + 2 * tx);
            // W: 16 units = 8 f32x2 pairs; identical address across warp
            const ulonglong2* wp =
                (const ulonglong2*)(ws + f * UU + 16 * ty);
            const ulonglong2 wa = wp[0];
            const ulonglong2 wb = wp[1];
            const ulonglong2 wc = wp[2];
            const ulonglong2 wd = wp[3];

            acc[0][0] = fma2(xa.x, wa.x, acc[0][0]);
            acc[0][1] = fma2(xa.x, wa.y, acc[0][1]);
            acc[0][2] = fma2(xa.x, wb.x, acc[0][2]);
            acc[0][3] = fma2(xa.x, wb.y, acc[0][3]);
            acc[0][4] = fma2(xa.x, wc.x, acc[0][4]);
            acc[0][5] = fma2(xa.x, wc.y, acc[0][5]);
            acc[0][6] = fma2(xa.x, wd.x, acc[0][6]);
            acc[0][7] = fma2(xa.x, wd.y, acc[0][7]);
            acc[1][0] = fma2(xa.y, wa.x, acc[1][0]);
            acc[1][1] = fma2(xa.y, wa.y, acc[1][1]);
            acc[1][2] = fma2(xa.y, wb.x, acc[1][2]);
            acc[1][3] = fma2(xa.y, wb.y, acc[1][3]);
            acc[1][4] = fma2(xa.y, wc.x, acc[1][4]);
            acc[1][5] = fma2(xa.y, wc.y, acc[1][5]);
            acc[1][6] = fma2(xa.y, wd.x, acc[1][6]);
            acc[1][7] = fma2(xa.y, wd.y, acc[1][7]);
        }
    }

    // epilogue: relu + second layer partial dot over this thread's 16 units
    float p0 = 0.0f, p1 = 0.0f;
#pragma unroll
    for (int p = 0; p < 8; ++p) {
        const int u = 16 * ty + 2 * p;
        const float b1lo = b1[u], b1hi = b1[u + 1];
        const float w2lo = W2[u], w2hi = W2[u + 1];
        const float2 h0 = unpack2(acc[0][p]);
        const float2 h1 = unpack2(acc[1][p]);
        p0 += fmaxf(h0.x + b1lo, 0.0f) * w2lo + fmaxf(h0.y + b1hi, 0.0f) * w2hi;
        p1 += fmaxf(h1.x + b1lo, 0.0f) * w2lo + fmaxf(h1.y + b1hi, 0.0f) * w2hi;
    }

    __syncthreads();
    red[ty][2 * tx + 0] = p0;
    red[ty][2 * tx + 1] = p1;
    if (nz) nzflag[lrow] = 1;
    __syncthreads();

    if (tid < TM) {
        float s = 0.0f;
#pragma unroll
        for (int j = 0; j < 8; ++j) s += red[j][tid];
        s += b2[0];
        g_scores[frame0 + tid] = nzflag[tid] ? s : -1.0e9f;
    }
}

// ---------------------------------------------------------------------------
// Kernel 2: per-batch top-k selection via 4x8-bit radix select on orderable
// uint keys. Ties (==threshold) taken by smallest index (jax top_k stable).
// ---------------------------------------------------------------------------
__global__ __launch_bounds__(256) void topk_kernel(const int* kptr)
{
    __shared__ unsigned keys[TT];
    __shared__ int      hist[256];
    __shared__ unsigned s_prefix;
    __shared__ int      s_remaining;

    const int b   = blockIdx.x;
    const int tid = threadIdx.x;

    int k = 64;
    if (kptr) {
        int kv = *kptr;
        if (kv > 0 && kv <= TT) k = kv;
        else {
            float kf = __int_as_float(kv);
            if (kf >= 1.0f && kf <= (float)TT) k = (int)kf;
        }
    }

    for (int i = tid; i < TT; i += 256) {
        unsigned u = __float_as_uint(g_scores[b * TT + i]);
        keys[i] = (u & 0x80000000u) ? ~u : (u | 0x80000000u);
    }
    if (tid == 0) { s_prefix = 0u; s_remaining = k; }
    __syncthreads();

    for (int pass = 3; pass >= 0; --pass) {
        hist[tid] = 0;
        __syncthreads();
        const unsigned mhi  = (pass == 3) ? 0u : (0xFFFFFFFFu << ((pass + 1) * 8));
        const unsigned pref = s_prefix;
        const int shift = pass * 8;
        for (int i = tid; i < TT; i += 256) {
            const unsigned ky = keys[i];
            if ((ky & mhi) == pref) atomicAdd(&hist[(ky >> shift) & 255], 1);
        }
        __syncthreads();
        if (tid == 0) {
            int rem = s_remaining, cum = 0, bin;
            for (bin = 255; bin >= 0; --bin) {
                const int c = hist[bin];
                if (cum + c >= rem) break;
                cum += c;
            }
            s_prefix    = pref | ((unsigned)bin << shift);
            s_remaining = rem - cum;
        }
        __syncthreads();
    }

    const unsigned thr = s_prefix;
    const int need = s_remaining;
    for (int i = tid; i < TT; i += 256) {
        const unsigned ky = keys[i];
        unsigned char sv = 0;
        if (ky > thr) sv = 1;
        else if (ky == thr) {
            int r = 0;
            for (int j = 0; j < i; ++j) r += (keys[j] == thr);
            sv = (r < need) ? 1 : 0;
        }
        g_sel[b * TT + i] = sv;
    }
}

// ---------------------------------------------------------------------------
// Kernel 3: out = sel ? x : 0. Reads x only for selected frames.
// ---------------------------------------------------------------------------
__global__ __launch_bounds__(256) void gather_kernel(
    const float* __restrict__ x, float* __restrict__ out)
{
    const int i = blockIdx.x * 256 + threadIdx.x;   // float4 index
    const int frame = i >> 7;                       // FF/4 = 128 float4/frame
    float4 v = make_float4(0.f, 0.f, 0.f, 0.f);
    if (g_sel[frame]) v = ((const float4*)x)[i];
    ((float4*)out)[i] = v;
}

// ---------------------------------------------------------------------------
extern "C" void kernel_launch(void* const* d_in, const int* in_sizes, int n_in,
                              void* d_out, int out_size)
{
    const float* x  = (const float*)d_in[0];
    const float* W1 = (const float*)d_in[1];
    const float* b1 = (const float*)d_in[2];
    const float* W2 = (const float*)d_in[3];
    const float* b2 = (const float*)d_in[4];
    const int*   kp = (n_in > 5) ? (const int*)d_in[5] : nullptr;

    score_kernel<<<(BB * TT) / TM, 256>>>(x, W1, b1, W2, b2);
    topk_kernel<<<BB, 256>>>(kp);
    gather_kernel<<<(BB * TT * FF / 4) / 256, 256>>>(x, (float*)d_out);
}

// round 3
// speedup vs baseline: 1.9638x; 1.2641x over previous
#include <cuda_runtime.h>

// RLFrameSelector: scores = relu(x@W1 + b1)@W2 + b2 (masked), per-batch top-k
// frame selection, out = x * sel.
//
// R3: score_kernel LDS-traffic cut 8wf -> 4wf per 16 FMA2 (4 frames/thread,
// un-duplicated x + ALU-pipe mov.b64 packing), double-buffered chunks with a
// single barrier per chunk. Target: FMA-pipe bound.

#define BB 32
#define TT 2048
#define FF 512
#define UU 128
#define TM 64        // frames per block
#define FC 16        // f-chunk
#define XST 68       // float stride per f-row in xs (272B, 16B-aligned)

__device__ float         g_scores[BB * TT];
__device__ unsigned char g_sel[BB * TT];

__device__ __forceinline__ unsigned long long fma2(unsigned long long a,
                                                   unsigned long long b,
                                                   unsigned long long c) {
    unsigned long long d;
    asm("fma.rn.f32x2 %0, %1, %2, %3;" : "=l"(d) : "l"(a), "l"(b), "l"(c));
    return d;
}

__device__ __forceinline__ unsigned long long pack2(float v) {
    unsigned long long d;
    asm("mov.b64 %0, {%1, %1};" : "=l"(d) : "f"(v));
    return d;
}

__device__ __forceinline__ float2 unpack2(unsigned long long v) {
    float2 r;
    asm("mov.b64 {%0, %1}, %2;" : "=f"(r.x), "=f"(r.y) : "l"(v));
    return r;
}

// ---------------------------------------------------------------------------
// Kernel 1: scores. Block = 256 threads.
//   tx = tid&15  -> frame quad (frames 4*tx .. 4*tx+3)
//   ty = tid>>4  -> units 8*ty .. 8*ty+7 (4 f32x2 u-pairs)
// Thread tile: 4 frames x 8 units = 16 f32x2 accumulators.
// Per f-step: 1 LDS.128 x (2 wf) + 2 LDS.128 W (1 wf each) + 4 ALU packs
//             + 16 fma.rn.f32x2.
// ---------------------------------------------------------------------------
__global__ __launch_bounds__(256, 3) void score_kernel(
    const float* __restrict__ x,  const float* __restrict__ W1,
    const float* __restrict__ b1, const float* __restrict__ W2,
    const float* __restrict__ b2)
{
    __shared__ float xs[2][FC * XST];      // [buf][f][t]  (transposed x)
    __shared__ float ws[2][FC * UU];       // [buf][f][u]
    __shared__ int   nzflag[TM];
    __shared__ float red[16][TM + 4];      // partial scores per ty-group

    const int tid = threadIdx.x;
    const int tx  = tid & 15;
    const int ty  = tid >> 4;
    const int frame0 = blockIdx.x * TM;

    // loader mapping: lrow = frame within block, lg = 4-float group of chunk
    const int lrow = tid >> 2;
    const int lg   = tid & 3;

    if (tid < TM) nzflag[tid] = 0;

    unsigned long long acc[4][4];
#pragma unroll
    for (int t = 0; t < 4; ++t)
#pragma unroll
        for (int p = 0; p < 4; ++p) acc[t][p] = 0ull;

    int nz = 0;
    const float* xrow = x + (size_t)(frame0 + lrow) * FF + 4 * lg;

    // ---- prologue: load + store chunk 0 into buffer 0
    float4 xv = *(const float4*)(xrow);
    const float4* wsrc = (const float4*)(W1);
    float4 wv0 = wsrc[tid];
    float4 wv1 = wsrc[tid + 256];
    nz |= (xv.x != 0.0f) | (xv.y != 0.0f) | (xv.z != 0.0f) | (xv.w != 0.0f);

    xs[0][(4 * lg + 0) * XST + lrow] = xv.x;
    xs[0][(4 * lg + 1) * XST + lrow] = xv.y;
    xs[0][(4 * lg + 2) * XST + lrow] = xv.z;
    xs[0][(4 * lg + 3) * XST + lrow] = xv.w;
    ((float4*)ws[0])[tid]       = wv0;
    ((float4*)ws[0])[tid + 256] = wv1;
    __syncthreads();

#pragma unroll 1
    for (int chunk = 0; chunk < FF / FC; ++chunk) {
        const int buf = chunk & 1;
        const bool more = (chunk < FF / FC - 1);

        if (more) {
            xv  = *(const float4*)(xrow + (chunk + 1) * FC);
            wsrc = (const float4*)(W1 + (chunk + 1) * FC * UU);
            wv0 = wsrc[tid];
            wv1 = wsrc[tid + 256];
        }

#pragma unroll
        for (int f = 0; f < FC; ++f) {
            const float4 xq = *(const float4*)(xs[buf] + f * XST + 4 * tx);
            const ulonglong2* wp =
                (const ulonglong2*)(ws[buf] + f * UU + 8 * ty);
            const ulonglong2 wa = wp[0];      // u-pairs 0,1
            const ulonglong2 wb = wp[1];      // u-pairs 2,3

            const unsigned long long x0 = pack2(xq.x);
            const unsigned long long x1 = pack2(xq.y);
            const unsigned long long x2 = pack2(xq.z);
            const unsigned long long x3 = pack2(xq.w);

            acc[0][0] = fma2(x0, wa.x, acc[0][0]);
            acc[0][1] = fma2(x0, wa.y, acc[0][1]);
            acc[0][2] = fma2(x0, wb.x, acc[0][2]);
            acc[0][3] = fma2(x0, wb.y, acc[0][3]);
            acc[1][0] = fma2(x1, wa.x, acc[1][0]);
            acc[1][1] = fma2(x1, wa.y, acc[1][1]);
            acc[1][2] = fma2(x1, wb.x, acc[1][2]);
            acc[1][3] = fma2(x1, wb.y, acc[1][3]);
            acc[2][0] = fma2(x2, wa.x, acc[2][0]);
            acc[2][1] = fma2(x2, wa.y, acc[2][1]);
            acc[2][2] = fma2(x2, wb.x, acc[2][2]);
            acc[2][3] = fma2(x2, wb.y, acc[2][3]);
            acc[3][0] = fma2(x3, wa.x, acc[3][0]);
            acc[3][1] = fma2(x3, wa.y, acc[3][1]);
            acc[3][2] = fma2(x3, wb.x, acc[3][2]);
            acc[3][3] = fma2(x3, wb.y, acc[3][3]);
        }

        if (more) {
            // chunk-1 reads of buf^1 finished at the previous barrier
            nz |= (xv.x != 0.0f) | (xv.y != 0.0f) |
                  (xv.z != 0.0f) | (xv.w != 0.0f);
            const int nbuf = buf ^ 1;
            xs[nbuf][(4 * lg + 0) * XST + lrow] = xv.x;
            xs[nbuf][(4 * lg + 1) * XST + lrow] = xv.y;
            xs[nbuf][(4 * lg + 2) * XST + lrow] = xv.z;
            xs[nbuf][(4 * lg + 3) * XST + lrow] = xv.w;
            ((float4*)ws[nbuf])[tid]       = wv0;
            ((float4*)ws[nbuf])[tid + 256] = wv1;
        }
        __syncthreads();
    }

    // epilogue: relu + second layer partial dot over this thread's 8 units
    float p[4] = {0.f, 0.f, 0.f, 0.f};
#pragma unroll
    for (int pi = 0; pi < 4; ++pi) {
        const int u = 8 * ty + 2 * pi;
        const float b1lo = b1[u], b1hi = b1[u + 1];
        const float w2lo = W2[u], w2hi = W2[u + 1];
#pragma unroll
        for (int t = 0; t < 4; ++t) {
            const float2 h = unpack2(acc[t][pi]);
            p[t] += fmaxf(h.x + b1lo, 0.0f) * w2lo
                  + fmaxf(h.y + b1hi, 0.0f) * w2hi;
        }
    }

    *(float4*)&red[ty][4 * tx] = make_float4(p[0], p[1], p[2], p[3]);
    if (nz) nzflag[lrow] = 1;
    __syncthreads();

    if (tid < TM) {
        float s = 0.0f;
#pragma unroll
        for (int j = 0; j < 16; ++j) s += red[j][tid];
        s += b2[0];
        g_scores[frame0 + tid] = nzflag[tid] ? s : -1.0e9f;
    }
}

// ---------------------------------------------------------------------------
// Kernel 2: per-batch top-k via 4x8-bit radix select on orderable uint keys.
// Ties (==threshold) taken by smallest index (jax top_k stable).
// ---------------------------------------------------------------------------
__global__ __launch_bounds__(256) void topk_kernel(const int* kptr)
{
    __shared__ unsigned keys[TT];
    __shared__ int      hist[256];
    __shared__ unsigned s_prefix;
    __shared__ int      s_remaining;

    const int b   = blockIdx.x;
    const int tid = threadIdx.x;

    int k = 64;
    if (kptr) {
        int kv = *kptr;
        if (kv > 0 && kv <= TT) k = kv;
        else {
            float kf = __int_as_float(kv);
            if (kf >= 1.0f && kf <= (float)TT) k = (int)kf;
        }
    }

    for (int i = tid; i < TT; i += 256) {
        unsigned u = __float_as_uint(g_scores[b * TT + i]);
        keys[i] = (u & 0x80000000u) ? ~u : (u | 0x80000000u);
    }
    if (tid == 0) { s_prefix = 0u; s_remaining = k; }
    __syncthreads();

    for (int pass = 3; pass >= 0; --pass) {
        hist[tid] = 0;
        __syncthreads();
        const unsigned mhi  = (pass == 3) ? 0u : (0xFFFFFFFFu << ((pass + 1) * 8));
        const unsigned pref = s_prefix;
        const int shift = pass * 8;
        for (int i = tid; i < TT; i += 256) {
            const unsigned ky = keys[i];
            if ((ky & mhi) == pref) atomicAdd(&hist[(ky >> shift) & 255], 1);
        }
        __syncthreads();
        if (tid == 0) {
            int rem = s_remaining, cum = 0, bin;
            for (bin = 255; bin >= 0; --bin) {
                const int c = hist[bin];
                if (cum + c >= rem) break;
                cum += c;
            }
            s_prefix    = pref | ((unsigned)bin << shift);
            s_remaining = rem - cum;
        }
        __syncthreads();
    }

    const unsigned thr = s_prefix;
    const int need = s_remaining;
    for (int i = tid; i < TT; i += 256) {
        const unsigned ky = keys[i];
        unsigned char sv = 0;
        if (ky > thr) sv = 1;
        else if (ky == thr) {
            int r = 0;
            for (int j = 0; j < i; ++j) r += (keys[j] == thr);
            sv = (r < need) ? 1 : 0;
        }
        g_sel[b * TT + i] = sv;
    }
}

// ---------------------------------------------------------------------------
// Kernel 3: out = sel ? x : 0. Reads x only for selected frames.
// ---------------------------------------------------------------------------
__global__ __launch_bounds__(256) void gather_kernel(
    const float* __restrict__ x, float* __restrict__ out)
{
    const int i = blockIdx.x * 256 + threadIdx.x;   // float4 index
    const int frame = i >> 7;                       // FF/4 = 128 float4/frame
    float4 v = make_float4(0.f, 0.f, 0.f, 0.f);
    if (g_sel[frame]) v = ((const float4*)x)[i];
    ((float4*)out)[i] = v;
}

// ---------------------------------------------------------------------------
extern "C" void kernel_launch(void* const* d_in, const int* in_sizes, int n_in,
                              void* d_out, int out_size)
{
    const float* x  = (const float*)d_in[0];
    const float* W1 = (const float*)d_in[1];
    const float* b1 = (const float*)d_in[2];
    const float* W2 = (const float*)d_in[3];
    const float* b2 = (const float*)d_in[4];
    const int*   kp = (n_in > 5) ? (const int*)d_in[5] : nullptr;

    score_kernel<<<(BB * TT) / TM, 256>>>(x, W1, b1, W2, b2);
    topk_kernel<<<BB, 256>>>(kp);
    gather_kernel<<<(BB * TT * FF / 4) / 256, 256>>>(x, (float*)d_out);
}